// round 11
// baseline (speedup 1.0000x reference)
#include <cuda_runtime.h>
#include <cuda_bf16.h>

// ---------------- LUT of the composite 3-step nonlinear map ----------------
// h(x) = f(f(f(x))) is a fixed scalar function (tables are runtime constants).
// Piecewise-linear, 192 intervals over [-6, 6] (step 1/16). erff saturates
// exactly in f32 well before |x|=6, so h is exactly affine outside; the
// unclamped-frac lerp on edge intervals extrapolates that exact line.

#define LUT_N        192
#define LUT_XMIN     (-6.0f)
#define LUT_STEP     0.0625f
#define LUT_INV_STEP 16.0f
#define LUT_OFF      96.0f

__device__ float2 g_lut[LUT_N];     // (h_i, h_{i+1} - h_i)

__device__ float h_eval(float x, const float* __restrict__ ang,
                        const float* __restrict__ vel) {
    const float S2 = 0.33333f * 0.33333f;
#pragma unroll 1
    for (int it = 0; it < 3; ++it) {
        float ia = (0.5f * (1.0f + erff(x * 0.70710678118654752f))) * 5.0f;
        float iv = (0.5f * (1.0f + erff(x))) * 5.0f;
        int ba = (int)floorf(ia);
        if (ba < 0) ba = 0; if (ba > 3) ba--; if (ba > 3) ba--;
        int bv = (int)floorf(iv);
        if (bv < 0) bv = 0; if (bv > 3) bv--; if (bv > 3) bv--;
        float pa = ia - (float)ba;
        float pv = iv - (float)bv;
        float A = (1.0f - pa) * ang[ba] + pa * ang[ba + 1];
        float V = (1.0f - pv) * vel[bv] + pv * vel[bv + 1];
        x = x + (V * cosf(A) + x * V * sinf(A)) * S2;
    }
    return x;
}

// One h_eval per thread (193 nodes), deltas from shared: halves the serial
// critical path of the LUT build vs two h_evals per thread.
__global__ void build_lut_kernel(const float* __restrict__ angles,
                                 const float* __restrict__ velocity) {
    __shared__ float sh[LUT_N + 1];
    int i = threadIdx.x;
    if (i <= LUT_N)
        sh[i] = h_eval(LUT_XMIN + (float)i * LUT_STEP, angles, velocity);
    __syncthreads();
    if (i < LUT_N)
        g_lut[i] = make_float2(sh[i], sh[i + 1] - sh[i]);
}

// ---------------- Main fused kernel ----------------
// Thread = (C = c*2+cf, os, batch-group of 8). 16 weight regs per thread.
// float2 LUT replicated 16x, half-warp interleaved -> every LDS.64 is the
// 2-phase minimum regardless of index randomness.

#define NPAIR    (512u * 49u)        // (C, os) pairs = 25088
#define BCHUNK   8
#define NBGRP    (256u / BCHUNK)     // 32
#define NTHREADS (NPAIR * NBGRP)     // 802,816
#define NBLOCKS  (NTHREADS / 256u)   // 3136
#define REP      16
#define MAGIC    8388608.0f          // 2^23

__global__ __launch_bounds__(256) void mac_tensor_unit_kernel(
    const float* __restrict__ data,      // [256, 256, 196]
    const float* __restrict__ in_w,      // [512, 196]
    const float* __restrict__ in_b,      // [512, 196]
    const float* __restrict__ out_w,     // [512, 196]
    const float* __restrict__ out_b,     // [512, 196]
    float* __restrict__ out)             // [256, 512, 49]
{
    __shared__ float2 s_lut[LUT_N * REP];   // 24KB

    unsigned gid  = blockIdx.x * 256u + threadIdx.x;
    unsigned pair = gid % NPAIR;            // consecutive across lanes -> coalesced
    unsigned bg   = gid / NPAIR;
    unsigned os   = pair % 49u;
    unsigned C    = pair / 49u;             // 0..511 = c*2+cf
    unsigned c    = C >> 1;
    unsigned b0   = bg * BCHUNK;

    // Batch-invariant weights (issued first; latency hides behind LUT build).
    // LUT index transform folded into expansion weights:
    //   t = (d*iw+ib)*16 + 96 = d*(iw*16) + (ib*16+96)
    float iw2[4], ib2[4], ow[4], ob[4];
#pragma unroll
    for (int sf = 0; sf < 4; ++sf) {
        unsigned off = C * 196u + (unsigned)sf * 49u + os;
        iw2[sf] = in_w[off];
        ib2[sf] = in_b[off];
        ow[sf]  = out_w[off];
        ob[sf]  = out_b[off];
    }
#pragma unroll
    for (int sf = 0; sf < 4; ++sf) {
        iw2[sf] = iw2[sf] * LUT_INV_STEP;
        ib2[sf] = fmaf(ib2[sf], LUT_INV_STEP, LUT_OFF);
    }

    {   // replicated LUT build: 3072 float2 slots, 12 per thread
#pragma unroll
        for (int j = 0; j < (LUT_N * REP) / 256; ++j) {
            int s = threadIdx.x + j * 256;
            s_lut[s] = g_lut[s >> 4];
        }
    }
    __syncthreads();

    const float2* lp = s_lut + (threadIdx.x & 15u);

    const float* dbase = data + (((b0 << 8) + c) * 196u + os);
    float*       obase = out  + (((b0 << 9) + C) * 49u + os);

    // Software pipeline over batches (branch-free prefetch: last iteration
    // re-reads batch 0 — an L1 hit, discarded).
    float dc[4];
#pragma unroll
    for (int sf = 0; sf < 4; ++sf) dc[sf] = dbase[sf * 49];

#pragma unroll 2
    for (int bi = 0; bi < BCHUNK; ++bi) {
        const float* dp = dbase + ((bi + 1) & (BCHUNK - 1)) * (256u * 196u);
        float dn[4];
#pragma unroll
        for (int sf = 0; sf < 4; ++sf) dn[sf] = dp[sf * 49];

        float acc = 0.0f;
#pragma unroll
        for (int sf = 0; sf < 4; ++sf) {
            // fused expansion + LUT index
            float t  = fmaf(dc[sf], iw2[sf], ib2[sf]);
            float tc = fminf(fmaxf(t, 0.0f), (float)(LUT_N - 1));
            // floor via round-down magic add: ff = 2^23 + floor(tc) exactly
            float ff = __fadd_rd(tc, MAGIC);
            float fi = ff - MAGIC;                 // floor(tc)
            int   ii = __float_as_int(ff) & 0xFF;  // floor(tc) < 256
            float fr = t - fi;                     // unclamped -> exact tails
            float2 e = lp[ii * REP];
            float x  = fmaf(fr, e.y, e.x);

            // attention gate (alg1) + reduce over sf
            float g   = fmaf(x, ow[sf], ob[sf]);
            float att = fmaf(__fdividef(g, 1.0f + fabsf(g)), 0.5f, 0.5f);
            acc = fmaf(x, att, acc);
        }

        obase[bi * (512u * 49u)] = acc;

#pragma unroll
        for (int sf = 0; sf < 4; ++sf) dc[sf] = dn[sf];
    }
}

extern "C" void kernel_launch(void* const* d_in, const int* in_sizes, int n_in,
                              void* d_out, int out_size) {
    const float* data     = (const float*)d_in[0];
    const float* in_w     = (const float*)d_in[1];
    const float* in_b     = (const float*)d_in[2];
    const float* out_w    = (const float*)d_in[3];
    const float* out_b    = (const float*)d_in[4];
    const float* angles   = (const float*)d_in[5];
    const float* velocity = (const float*)d_in[6];
    float* out = (float*)d_out;

    build_lut_kernel<<<1, 256>>>(angles, velocity);
    mac_tensor_unit_kernel<<<NBLOCKS, 256>>>(data, in_w, in_b, out_w, out_b, out);
}

// round 15
// speedup vs baseline: 1.0523x; 1.0523x over previous
#include <cuda_runtime.h>
#include <cuda_bf16.h>

// ---------------- LUT of the composite 3-step nonlinear map ----------------
// h(x) = f(f(f(x))) is a fixed scalar function (tables are runtime constants).
// Piecewise-linear, 192 intervals over [-6, 6] (step 1/16). erff saturates
// exactly in f32 well before |x|=6, so h is exactly affine outside; the
// unclamped-frac lerp on edge intervals extrapolates that exact line.

#define LUT_N        192
#define LUT_XMIN     (-6.0f)
#define LUT_STEP     0.0625f
#define LUT_INV_STEP 16.0f
#define LUT_OFF      96.0f

__device__ float2 g_lut[LUT_N];     // (h_i, h_{i+1} - h_i)

__device__ float h_eval(float x, const float* __restrict__ ang,
                        const float* __restrict__ vel) {
    const float S2 = 0.33333f * 0.33333f;
#pragma unroll 1
    for (int it = 0; it < 3; ++it) {
        float ia = (0.5f * (1.0f + erff(x * 0.70710678118654752f))) * 5.0f;
        float iv = (0.5f * (1.0f + erff(x))) * 5.0f;
        int ba = (int)floorf(ia);
        if (ba < 0) ba = 0; if (ba > 3) ba--; if (ba > 3) ba--;
        int bv = (int)floorf(iv);
        if (bv < 0) bv = 0; if (bv > 3) bv--; if (bv > 3) bv--;
        float pa = ia - (float)ba;
        float pv = iv - (float)bv;
        float A = (1.0f - pa) * ang[ba] + pa * ang[ba + 1];
        float V = (1.0f - pv) * vel[bv] + pv * vel[bv + 1];
        // A in [0, 2*pi]: __sincosf abs error ~2^-21 here, negligible vs lerp error
        float sA, cA;
        __sincosf(A, &sA, &cA);
        x = x + (V * cA + x * V * sA) * S2;
    }
    return x;
}

// One h_eval per thread (193 nodes), deltas via shared: short serial prologue.
__global__ void build_lut_kernel(const float* __restrict__ angles,
                                 const float* __restrict__ velocity) {
    __shared__ float sh[LUT_N + 1];
    int i = threadIdx.x;
    if (i <= LUT_N)
        sh[i] = h_eval(LUT_XMIN + (float)i * LUT_STEP, angles, velocity);
    __syncthreads();
    if (i < LUT_N)
        g_lut[i] = make_float2(sh[i], sh[i + 1] - sh[i]);
}

// ---------------- Main fused kernel ----------------
// Thread = (C = c*2+cf, os, batch-group of 8). 16 weight regs per thread.
// float2 LUT replicated 16x, half-warp interleaved -> every LDS.64 is the
// 2-phase minimum regardless of index randomness.
// __launch_bounds__(256,7): cap regs ~36 -> 7 blocks/SM -> 56 warps (87% occ);
// latency hiding comes from occupancy, so no manual prefetch pipeline needed.

#define NPAIR    (512u * 49u)        // (C, os) pairs = 25088
#define BCHUNK   8
#define NBGRP    (256u / BCHUNK)     // 32
#define NTHREADS (NPAIR * NBGRP)     // 802,816
#define NBLOCKS  (NTHREADS / 256u)   // 3136
#define REP      16
#define MAGIC    8388608.0f          // 2^23

__global__ __launch_bounds__(256, 7) void mac_tensor_unit_kernel(
    const float* __restrict__ data,      // [256, 256, 196]
    const float* __restrict__ in_w,      // [512, 196]
    const float* __restrict__ in_b,      // [512, 196]
    const float* __restrict__ out_w,     // [512, 196]
    const float* __restrict__ out_b,     // [512, 196]
    float* __restrict__ out)             // [256, 512, 49]
{
    __shared__ float2 s_lut[LUT_N * REP];   // 24KB

    unsigned gid  = blockIdx.x * 256u + threadIdx.x;
    unsigned pair = gid % NPAIR;            // consecutive across lanes -> coalesced
    unsigned bg   = gid / NPAIR;
    unsigned os   = pair % 49u;
    unsigned C    = pair / 49u;             // 0..511 = c*2+cf
    unsigned c    = C >> 1;
    unsigned b0   = bg * BCHUNK;

    // Batch-invariant weights (issued first; latency hides behind LUT build).
    // LUT index transform folded into the expansion weights:
    //   t = (d*iw+ib)*16 + 96 = d*(iw*16) + (ib*16+96)
    float iw2[4], ib2[4], ow[4], ob[4];
#pragma unroll
    for (int sf = 0; sf < 4; ++sf) {
        unsigned off = C * 196u + (unsigned)sf * 49u + os;
        iw2[sf] = in_w[off];
        ib2[sf] = in_b[off];
        ow[sf]  = out_w[off];
        ob[sf]  = out_b[off];
    }
#pragma unroll
    for (int sf = 0; sf < 4; ++sf) {
        iw2[sf] = iw2[sf] * LUT_INV_STEP;
        ib2[sf] = fmaf(ib2[sf], LUT_INV_STEP, LUT_OFF);
    }

    {   // replicated LUT build: 3072 float2 slots, 12 per thread
#pragma unroll
        for (int j = 0; j < (LUT_N * REP) / 256; ++j) {
            int s = threadIdx.x + j * 256;
            s_lut[s] = g_lut[s >> 4];
        }
    }
    __syncthreads();

    const float2* lp = s_lut + (threadIdx.x & 15u);

    const float* dbase = data + (((b0 << 8) + c) * 196u + os);
    float*       obase = out  + (((b0 << 9) + C) * 49u + os);

#pragma unroll 1
    for (int bi = 0; bi < BCHUNK; ++bi) {
        const float* dp = dbase + bi * (256u * 196u);
        float d0 = dp[0];
        float d1 = dp[49];
        float d2 = dp[98];
        float d3 = dp[147];

        float acc = 0.0f;
        float dd[4] = {d0, d1, d2, d3};
#pragma unroll
        for (int sf = 0; sf < 4; ++sf) {
            // fused expansion + LUT index
            float t  = fmaf(dd[sf], iw2[sf], ib2[sf]);
            float tc = fminf(fmaxf(t, 0.0f), (float)(LUT_N - 1));
            // floor via round-down magic add: ff = 2^23 + floor(tc) exactly
            float ff = __fadd_rd(tc, MAGIC);
            float fi = ff - MAGIC;                 // floor(tc)
            int   ii = __float_as_int(ff) & 0xFF;  // floor(tc) < 256
            float fr = t - fi;                     // unclamped -> exact tails
            float2 e = lp[ii * REP];
            float x  = fmaf(fr, e.y, e.x);

            // attention gate (alg1) + reduce over sf
            float g   = fmaf(x, ow[sf], ob[sf]);
            float att = fmaf(__fdividef(g, 1.0f + fabsf(g)), 0.5f, 0.5f);
            acc = fmaf(x, att, acc);
        }

        obase[bi * (512u * 49u)] = acc;
    }
}

extern "C" void kernel_launch(void* const* d_in, const int* in_sizes, int n_in,
                              void* d_out, int out_size) {
    const float* data     = (const float*)d_in[0];
    const float* in_w     = (const float*)d_in[1];
    const float* in_b     = (const float*)d_in[2];
    const float* out_w    = (const float*)d_in[3];
    const float* out_b    = (const float*)d_in[4];
    const float* angles   = (const float*)d_in[5];
    const float* velocity = (const float*)d_in[6];
    float* out = (float*)d_out;

    build_lut_kernel<<<1, 256>>>(angles, velocity);
    mac_tensor_unit_kernel<<<NBLOCKS, 256>>>(data, in_w, in_b, out_w, out_b, out);
}

// round 16
// speedup vs baseline: 1.1164x; 1.0609x over previous
#include <cuda_runtime.h>
#include <cuda_bf16.h>

// ---------------- LUT of the composite 3-step nonlinear map ----------------
// h(x) = f(f(f(x))) is a fixed scalar function (tables are runtime constants).
// Piecewise-linear, 192 intervals over [-6, 6] (step 1/16). erff saturates
// exactly in f32 well before |x|=6, so h is exactly affine outside; the
// unclamped-frac lerp on edge intervals extrapolates that exact line.

#define LUT_N        192
#define LUT_XMIN     (-6.0f)
#define LUT_STEP     0.0625f
#define LUT_INV_STEP 16.0f
#define LUT_OFF      96.0f

__device__ float2 g_lut[LUT_N];     // (h_i, h_{i+1} - h_i)

__device__ float h_eval(float x, const float* __restrict__ ang,
                        const float* __restrict__ vel) {
    const float S2 = 0.33333f * 0.33333f;
#pragma unroll 1
    for (int it = 0; it < 3; ++it) {
        float ia = (0.5f * (1.0f + erff(x * 0.70710678118654752f))) * 5.0f;
        float iv = (0.5f * (1.0f + erff(x))) * 5.0f;
        int ba = (int)floorf(ia);
        if (ba < 0) ba = 0; if (ba > 3) ba--; if (ba > 3) ba--;
        int bv = (int)floorf(iv);
        if (bv < 0) bv = 0; if (bv > 3) bv--; if (bv > 3) bv--;
        float pa = ia - (float)ba;
        float pv = iv - (float)bv;
        float A = (1.0f - pa) * ang[ba] + pa * ang[ba + 1];
        float V = (1.0f - pv) * vel[bv] + pv * vel[bv + 1];
        // A in [0, 2*pi]: __sincosf abs error ~2^-21 here, negligible vs lerp error
        float sA, cA;
        __sincosf(A, &sA, &cA);
        x = x + (V * cA + x * V * sA) * S2;
    }
    return x;
}

// One h_eval per thread (193 nodes), deltas via shared: short serial prologue.
__global__ void build_lut_kernel(const float* __restrict__ angles,
                                 const float* __restrict__ velocity) {
    __shared__ float sh[LUT_N + 1];
    int i = threadIdx.x;
    if (i <= LUT_N)
        sh[i] = h_eval(LUT_XMIN + (float)i * LUT_STEP, angles, velocity);
    __syncthreads();
    if (i < LUT_N)
        g_lut[i] = make_float2(sh[i], sh[i + 1] - sh[i]);
}

// ---------------- Main fused kernel ----------------
// Thread = (C = c*2+cf, os, batch-group of 16). 16 weight regs per thread.
// float2 LUT replicated 16x, half-warp interleaved -> every LDS.64 is the
// 2-phase minimum regardless of index randomness. Guarded software prefetch
// hides the loop-head LDG latency (best measured structure, R10).

#define NPAIR    (512u * 49u)        // (C, os) pairs = 25088
#define BCHUNK   16
#define NBGRP    (256u / BCHUNK)     // 16
#define NTHREADS (NPAIR * NBGRP)     // 401,408
#define NBLOCKS  (NTHREADS / 256u)   // 1568
#define REP      16
#define MAGIC    8388608.0f          // 2^23

__global__ __launch_bounds__(256) void mac_tensor_unit_kernel(
    const float* __restrict__ data,      // [256, 256, 196]
    const float* __restrict__ in_w,      // [512, 196]
    const float* __restrict__ in_b,      // [512, 196]
    const float* __restrict__ out_w,     // [512, 196]
    const float* __restrict__ out_b,     // [512, 196]
    float* __restrict__ out)             // [256, 512, 49]
{
    __shared__ float2 s_lut[LUT_N * REP];   // 24KB

    unsigned gid  = blockIdx.x * 256u + threadIdx.x;
    unsigned pair = gid % NPAIR;            // consecutive across lanes -> coalesced
    unsigned bg   = gid / NPAIR;
    unsigned os   = pair % 49u;
    unsigned C    = pair / 49u;             // 0..511 = c*2+cf
    unsigned c    = C >> 1;
    unsigned b0   = bg * BCHUNK;

    // Batch-invariant weights (issued first; latency hides behind LUT build).
    // LUT index transform folded into the expansion weights:
    //   t = (d*iw+ib)*16 + 96 = d*(iw*16) + (ib*16+96)
    float iw2[4], ib2[4], ow[4], ob[4];
#pragma unroll
    for (int sf = 0; sf < 4; ++sf) {
        unsigned off = C * 196u + (unsigned)sf * 49u + os;
        iw2[sf] = in_w[off];
        ib2[sf] = in_b[off];
        ow[sf]  = out_w[off];
        ob[sf]  = out_b[off];
    }
#pragma unroll
    for (int sf = 0; sf < 4; ++sf) {
        iw2[sf] = iw2[sf] * LUT_INV_STEP;
        ib2[sf] = fmaf(ib2[sf], LUT_INV_STEP, LUT_OFF);
    }

    {   // replicated LUT build: 3072 float2 slots, 12 per thread
#pragma unroll
        for (int j = 0; j < (LUT_N * REP) / 256; ++j) {
            int s = threadIdx.x + j * 256;
            s_lut[s] = g_lut[s >> 4];
        }
    }
    __syncthreads();

    const char* lp = (const char*)(s_lut + (threadIdx.x & 15u));

    const float* dbase = data + (((b0 << 8) + c) * 196u + os);
    float*       obase = out  + (((b0 << 9) + C) * 49u + os);

    // Software pipeline: prefetch next batch's data while computing current.
    float dc[4];
#pragma unroll
    for (int sf = 0; sf < 4; ++sf) dc[sf] = dbase[sf * 49];

#pragma unroll 1
    for (int bi = 0; bi < BCHUNK; ++bi) {
        float dn[4];
        if (bi + 1 < BCHUNK) {
            const float* dp = dbase + (bi + 1) * (256u * 196u);
#pragma unroll
            for (int sf = 0; sf < 4; ++sf) dn[sf] = dp[sf * 49];
        }

        float acc = 0.0f;
#pragma unroll
        for (int sf = 0; sf < 4; ++sf) {
            // fused expansion + LUT index
            float t  = fmaf(dc[sf], iw2[sf], ib2[sf]);
            float tc = fminf(fmaxf(t, 0.0f), (float)(LUT_N - 1));
            // floor via round-down magic add: ff = 2^23 + floor(tc) exactly
            float ff = __fadd_rd(tc, MAGIC);
            float fi = ff - MAGIC;                       // floor(tc)
            unsigned bo = (__float_as_uint(ff) & 0xFFu) << 7;  // ii*REP*8 bytes
            float fr = t - fi;                           // unclamped -> exact tails
            float2 e = *(const float2*)(lp + bo);
            float x  = fmaf(fr, e.y, e.x);

            // attention gate (alg1) + reduce over sf
            float g   = fmaf(x, ow[sf], ob[sf]);
            float att = fmaf(__fdividef(g, 1.0f + fabsf(g)), 0.5f, 0.5f);
            acc = fmaf(x, att, acc);
        }

        obase[bi * (512u * 49u)] = acc;

#pragma unroll
        for (int sf = 0; sf < 4; ++sf) dc[sf] = dn[sf];
    }
}

extern "C" void kernel_launch(void* const* d_in, const int* in_sizes, int n_in,
                              void* d_out, int out_size) {
    const float* data     = (const float*)d_in[0];
    const float* in_w     = (const float*)d_in[1];
    const float* in_b     = (const float*)d_in[2];
    const float* out_w    = (const float*)d_in[3];
    const float* out_b    = (const float*)d_in[4];
    const float* angles   = (const float*)d_in[5];
    const float* velocity = (const float*)d_in[6];
    float* out = (float*)d_out;

    build_lut_kernel<<<1, 256>>>(angles, velocity);
    mac_tensor_unit_kernel<<<NBLOCKS, 256>>>(data, in_w, in_b, out_w, out_b, out);
}